// round 15
// baseline (speedup 1.0000x reference)
#include <cuda_runtime.h>
#include <cuda_bf16.h>
#include <cstdint>
#include <math.h>

#define BB   8
#define CC   128
#define OO   128
#define HH   64
#define WW   64
#define HW   4096
#define NPIX 32768
#define CKK  1152
#define NOM  27
#define OMM  32                // padded M for om GEMM

// ---------------- device scratch (allocation-free rule) ----------------
__device__ __align__(16) unsigned short g_Wph[OO * CKK];
__device__ __align__(16) unsigned short g_Wpl[OO * CKK];
__device__ __align__(16) unsigned short g_WomH[OMM * CKK];
__device__ __align__(16) unsigned short g_WomL[OMM * CKK];
__device__ float   g_om[NOM * NPIX];
__device__ float4  g_w4[BB * 9 * HW];
__device__ ushort4 g_idx[BB * 9 * HW];

// ============================================================================
// common helpers
// ============================================================================
__device__ __forceinline__ uint32_t smem_u32(const void* p) {
    uint32_t a;
    asm("{ .reg .u64 t; cvta.to.shared.u64 t, %1; cvt.u32.u64 %0, t; }" : "=r"(a) : "l"(p));
    return a;
}
__device__ __forceinline__ void ldm_x4(uint32_t* r, uint32_t addr) {
    asm volatile("ldmatrix.sync.aligned.m8n8.x4.shared.b16 {%0,%1,%2,%3}, [%4];"
                 : "=r"(r[0]), "=r"(r[1]), "=r"(r[2]), "=r"(r[3]) : "r"(addr));
}
__device__ __forceinline__ void mma_bf16(float* c, const uint32_t* a, uint32_t b0, uint32_t b1) {
    asm volatile("mma.sync.aligned.m16n8k16.row.col.f32.bf16.bf16.f32 "
                 "{%0,%1,%2,%3}, {%4,%5,%6,%7}, {%8,%9}, {%0,%1,%2,%3};"
                 : "+f"(c[0]), "+f"(c[1]), "+f"(c[2]), "+f"(c[3])
                 : "r"(a[0]), "r"(a[1]), "r"(a[2]), "r"(a[3]), "r"(b0), "r"(b1));
}
__device__ __forceinline__ void bf16_split(float v, unsigned short& h, unsigned short& l) {
    const __nv_bfloat16 hb = __float2bfloat16(v);
    h = __bfloat16_as_ushort(hb);
    l = __bfloat16_as_ushort(__float2bfloat16(v - __bfloat162float(hb)));
}

// ============================================================================
// Kernel 0a/0b: weight permute + bf16 hi/lo split (unchanged)
// ============================================================================
__global__ __launch_bounds__(256)
void prep_w(const float* __restrict__ w) {
    const int i = blockIdx.x * 256 + threadIdx.x;
    if (i < OO * CKK) {
        const int o = i / CKK;
        const int kk = i - o * CKK;
        const int k = kk >> 7;
        const int c = kk & 127;
        unsigned short h, l;
        bf16_split(w[(size_t)o * CKK + c * 9 + k], h, l);
        g_Wph[i] = h; g_Wpl[i] = l;
    }
}
__global__ __launch_bounds__(256)
void prep_wom(const float* __restrict__ w_om) {
    const int i = blockIdx.x * 256 + threadIdx.x;
    if (i < OMM * CKK) {
        const int o = i / CKK;
        const int kk = i - o * CKK;
        const int t = kk >> 7;
        const int c = kk & 127;
        const float v = (o < NOM) ? w_om[(size_t)o * CKK + c * 9 + t] : 0.f;
        unsigned short h, l;
        bf16_split(v, h, l);
        g_WomH[i] = h; g_WomL[i] = l;
    }
}

// ============================================================================
// Kernel 1a: om conv as bf16 tensor GEMM (unchanged from R11 lineage)
// ============================================================================
#define BKC  16
#define BSTU 24
#define NIT  (CKK / BKC)        // 72

__global__ __launch_bounds__(256)
void om_gemm(const float* __restrict__ x) {
    __shared__ __align__(16) unsigned short OAh[2][OMM * BSTU];
    __shared__ __align__(16) unsigned short OAl[2][OMM * BSTU];
    __shared__ __align__(16) unsigned short OBh[2][128 * BSTU];
    __shared__ __align__(16) unsigned short OBl[2][128 * BSTU];

    const int tid = threadIdx.x;
    const int wid = tid >> 5;
    const int lid = tid & 31;
    const int n0 = blockIdx.x * 128;

    const int bimg = n0 >> 12;
    const int p0 = n0 & 4095;
    const float* __restrict__ xbase = x + (size_t)(bimg * CC) * HW;

    const int arow = tid >> 1;
    const int ahalf = tid & 1;
    const int px = tid & 127;
    const int bh = tid >> 7;
    const int pj = p0 + px;
    const int y = pj >> 6;
    const int xx = pj & 63;

    const int mid = wid >> 2;
    const int nq = wid & 3;
    const int m0 = mid * 16;
    const uint32_t aOff =
        (uint32_t)((m0 + (lid & 7) + ((lid >> 3) & 1) * 8) * 48 + ((lid >> 4) & 1) * 16);
    const uint32_t bOff =
        (uint32_t)(((lid & 7) + ((lid >> 4) & 1) * 8) * 48 + ((lid >> 3) & 1) * 16);
    const uint32_t aHiS[2] = { smem_u32(OAh[0]) + aOff, smem_u32(OAh[1]) + aOff };
    const uint32_t aLoS[2] = { smem_u32(OAl[0]) + aOff, smem_u32(OAl[1]) + aOff };
    const uint32_t bHiS[2] = { smem_u32(OBh[0]) + bOff, smem_u32(OBh[1]) + bOff };
    const uint32_t bLoS[2] = { smem_u32(OBl[0]) + bOff, smem_u32(OBl[1]) + bOff };

    float acc[4][4];
#pragma unroll
    for (int i = 0; i < 4; ++i)
#pragma unroll
        for (int j = 0; j < 4; ++j) acc[i][j] = 0.f;

    auto prefetch = [&](int j, uint4& pAh, uint4& pAl, uint4& pBh, uint4& pBl) {
        const int ck0 = j * BKC;
        if (tid < 64) {
            const size_t gi = (size_t)arow * CKK + ck0 + ahalf * 8;
            pAh = *(const uint4*)(g_WomH + gi);
            pAl = *(const uint4*)(g_WomL + gi);
        }
        const int t = j >> 3;
        const int dy = t / 3 - 1;
        const int dx = t - (t / 3) * 3 - 1;
        const int yy = y + dy;
        const int xxx = xx + dx;
        const bool ok = (yy >= 0) & (yy < HH) & (xxx >= 0) & (xxx < WW);
        const int off = ok ? yy * WW + xxx : 0;
        const int cbase = ((j & 7) * 16) + bh * 8;
        const float* __restrict__ xc = xbase + (size_t)cbase * HW + off;
        unsigned short hu[8], lu[8];
#pragma unroll
        for (int j2 = 0; j2 < 8; ++j2) {
            const float v = ok ? __ldg(xc) : 0.f;
            bf16_split(v, hu[j2], lu[j2]);
            xc += HW;
        }
        pBh = make_uint4((uint32_t)hu[0] | ((uint32_t)hu[1] << 16),
                         (uint32_t)hu[2] | ((uint32_t)hu[3] << 16),
                         (uint32_t)hu[4] | ((uint32_t)hu[5] << 16),
                         (uint32_t)hu[6] | ((uint32_t)hu[7] << 16));
        pBl = make_uint4((uint32_t)lu[0] | ((uint32_t)lu[1] << 16),
                         (uint32_t)lu[2] | ((uint32_t)lu[3] << 16),
                         (uint32_t)lu[4] | ((uint32_t)lu[5] << 16),
                         (uint32_t)lu[6] | ((uint32_t)lu[7] << 16));
    };
    auto store_stage = [&](int dst, const uint4& pAh, const uint4& pAl,
                           const uint4& pBh, const uint4& pBl) {
        if (tid < 64) {
            *(uint4*)(OAh[dst] + arow * BSTU + ahalf * 8) = pAh;
            *(uint4*)(OAl[dst] + arow * BSTU + ahalf * 8) = pAl;
        }
        *(uint4*)(OBh[dst] + px * BSTU + bh * 8) = pBh;
        *(uint4*)(OBl[dst] + px * BSTU + bh * 8) = pBl;
    };

    {
        uint4 a0, a1, b0, b1;
        prefetch(0, a0, a1, b0, b1);
        store_stage(0, a0, a1, b0, b1);
    }
    __syncthreads();

    int s = 0;
    for (int it = 0; it < NIT; ++it) {
        uint4 pAh, pAl, pBh, pBl;
        const bool has_next = (it + 1 < NIT);
        if (has_next) prefetch(it + 1, pAh, pAl, pBh, pBl);

        uint32_t fAh[4], fAl[4];
        ldm_x4(fAh, aHiS[s]);
        ldm_x4(fAl, aLoS[s]);
#pragma unroll
        for (int pt = 0; pt < 2; ++pt) {
            uint32_t fBh[4], fBl[4];
            const uint32_t boff = (uint32_t)((nq * 32 + pt * 16) * 48);
            ldm_x4(fBh, bHiS[s] + boff);
            ldm_x4(fBl, bLoS[s] + boff);
            mma_bf16(acc[2 * pt], fAh, fBh[0], fBh[1]);
            mma_bf16(acc[2 * pt], fAh, fBl[0], fBl[1]);
            mma_bf16(acc[2 * pt], fAl, fBh[0], fBh[1]);
            mma_bf16(acc[2 * pt + 1], fAh, fBh[2], fBh[3]);
            mma_bf16(acc[2 * pt + 1], fAh, fBl[2], fBl[3]);
            mma_bf16(acc[2 * pt + 1], fAl, fBh[2], fBh[3]);
        }

        if (has_next) store_stage(s ^ 1, pAh, pAl, pBh, pBl);
        __syncthreads();
        s ^= 1;
    }

    const int r = lid >> 2;
    const int q = lid & 3;
    const int oA = m0 + r;
    const int oB = m0 + r + 8;
#pragma unroll
    for (int nt = 0; nt < 4; ++nt) {
        const int pxo = nq * 32 + (nt >> 1) * 16 + (nt & 1) * 8 + 2 * q;
        if (oA < NOM)
            *(float2*)(g_om + (size_t)oA * NPIX + n0 + pxo) = make_float2(acc[nt][0], acc[nt][1]);
        if (oB < NOM)
            *(float2*)(g_om + (size_t)oB * NPIX + n0 + pxo) = make_float2(acc[nt][2], acc[nt][3]);
    }
}

// ============================================================================
// Kernel 1b: add bias, softmax mask, bilinear weights + offsets (unchanged)
// ============================================================================
__global__ __launch_bounds__(256)
void om_final(const float* __restrict__ b_om) {
    const int bp = blockIdx.x * 256 + threadIdx.x;
    const int b = bp >> 12;
    const int p = bp & 4095;
    const int y = p >> 6;
    const int xx = p & 63;

    float acc[NOM];
#pragma unroll
    for (int oc = 0; oc < NOM; ++oc)
        acc[oc] = __ldg(b_om + oc) + g_om[(size_t)oc * NPIX + bp];

    float mx = acc[18];
#pragma unroll
    for (int k = 1; k < 9; ++k) mx = fmaxf(mx, acc[18 + k]);
    float e[9], s = 0.f;
#pragma unroll
    for (int k = 0; k < 9; ++k) { e[k] = expf(acc[18 + k] - mx); s += e[k]; }
    const float inv = 1.f / s;

#pragma unroll
    for (int k = 0; k < 9; ++k) {
        const float m = e[k] * inv;
        const float py = (float)(y - 1 + k / 3) + acc[2 * k];
        const float px = (float)(xx - 1 + k % 3) + acc[2 * k + 1];
        const float fy = floorf(py), fx = floorf(px);
        const int y0 = (int)fy, x0 = (int)fx;
        const float wy1 = py - fy, wx1 = px - fx;
        const float wy0 = 1.f - wy1, wx0 = 1.f - wx1;
        const bool vy0 = (y0 >= 0) & (y0 < HH);
        const bool vy1 = (y0 >= -1) & (y0 < HH - 1);
        const bool vx0 = (x0 >= 0) & (x0 < WW);
        const bool vx1 = (x0 >= -1) & (x0 < WW - 1);
        float4 w4;
        w4.x = (vy0 & vx0) ? wy0 * wx0 * m : 0.f;
        w4.y = (vy0 & vx1) ? wy0 * wx1 * m : 0.f;
        w4.z = (vy1 & vx0) ? wy1 * wx0 * m : 0.f;
        w4.w = (vy1 & vx1) ? wy1 * wx1 * m : 0.f;
        const int y0c = min(max(y0, 0), HH - 1);
        const int y1c = min(max(y0 + 1, 0), HH - 1);
        const int x0c = min(max(x0, 0), WW - 1);
        const int x1c = min(max(x0 + 1, 0), WW - 1);
        ushort4 s4;
        s4.x = (unsigned short)(y0c * WW + x0c);
        s4.y = (unsigned short)(y0c * WW + x1c);
        s4.z = (unsigned short)(y1c * WW + x0c);
        s4.w = (unsigned short)(y1c * WW + x1c);
        const int idx = (b * 9 + k) * HW + p;
        g_w4[idx] = w4;
        g_idx[idx] = s4;
    }
}

// ============================================================================
// Kernel 2: main bf16 split GEMM — NEW TILE: 128 o x 64 px per CTA, grid 512,
// 3 CTAs/SM (acc halves to 32 regs). Gather traffic unchanged (o not split);
// per-thread producer work halves; A re-reads double (L2-resident, cheap).
// ============================================================================
__global__ __launch_bounds__(256, 3)
void gemm_mma(const float* __restrict__ x, const float* __restrict__ bias,
              float* __restrict__ out) {
    __shared__ __align__(16) unsigned short Ahi[2][128 * 24];
    __shared__ __align__(16) unsigned short Alo[2][128 * 24];
    __shared__ __align__(16) unsigned short Bhi[2][64 * 24];
    __shared__ __align__(16) unsigned short Blo[2][64 * 24];

    const int tid = threadIdx.x;
    const int wid = tid >> 5;
    const int lid = tid & 31;
    const int bp0 = blockIdx.x * 64;

    const int bimg = bp0 >> 12;
    const int p0 = bp0 & 4095;
    const int bimg9 = bimg * 9;
    const float* __restrict__ xb = x + (size_t)(bimg * CC) * HW;

    // producers: A = 128 rows x 16 kk (2 halves); B = 64 px x 4 c-quads
    const int arow = tid >> 1;
    const int ahalf = tid & 1;
    const int px = tid & 63;
    const int qd = tid >> 6;            // 0..3: 4 channels each
    const int pj = p0 + px;

    // consumers: 4(m) x 2(n) warps, each 32o x 32px
    const int mid = wid >> 1;
    const int nq = wid & 1;
    const int m0 = mid * 32;
    const uint32_t aOff =
        (uint32_t)((m0 + (lid & 7) + ((lid >> 3) & 1) * 8) * 48 + ((lid >> 4) & 1) * 16);
    const uint32_t bOff =
        (uint32_t)(((lid & 7) + ((lid >> 4) & 1) * 8) * 48 + ((lid >> 3) & 1) * 16);
    const uint32_t aHiS[2] = { smem_u32(Ahi[0]) + aOff, smem_u32(Ahi[1]) + aOff };
    const uint32_t aLoS[2] = { smem_u32(Alo[0]) + aOff, smem_u32(Alo[1]) + aOff };
    const uint32_t bHiS[2] = { smem_u32(Bhi[0]) + bOff, smem_u32(Bhi[1]) + bOff };
    const uint32_t bLoS[2] = { smem_u32(Blo[0]) + bOff, smem_u32(Blo[1]) + bOff };

    // acc[f*4 + pt*2 + n8]: f = m-frag (0..1), pt = 16px tile (0..1), n8 (0..1)
    float acc[8][4];
#pragma unroll
    for (int i = 0; i < 8; ++i)
#pragma unroll
        for (int j = 0; j < 4; ++j) acc[i][j] = 0.f;

    int kcur = -1;
    float4 cw4;
    ushort4 cidx;

    auto prefetch = [&](int j, uint4& pAh, uint4& pAl, uint2& pBh, uint2& pBl) {
        const int ck0 = j * BKC;
        const size_t gi = (size_t)arow * CKK + ck0 + ahalf * 8;
        pAh = *(const uint4*)(g_Wph + gi);
        pAl = *(const uint4*)(g_Wpl + gi);

        const int kn = j >> 3;
        if (kn != kcur) {
            kcur = kn;
            const int t = (bimg9 + kn) * HW + pj;
            cw4 = __ldg(&g_w4[t]);
            cidx = __ldg(&g_idx[t]);
        }
        const int cbase = ((j & 7) * 16) + qd * 4;
        const float* __restrict__ xc = xb + (size_t)cbase * HW;
        unsigned short hu[4], lu[4];
#pragma unroll
        for (int j2 = 0; j2 < 4; ++j2) {
            const float v = cw4.x * __ldg(xc + cidx.x) + cw4.y * __ldg(xc + cidx.y)
                          + cw4.z * __ldg(xc + cidx.z) + cw4.w * __ldg(xc + cidx.w);
            bf16_split(v, hu[j2], lu[j2]);
            xc += HW;
        }
        pBh = make_uint2((uint32_t)hu[0] | ((uint32_t)hu[1] << 16),
                         (uint32_t)hu[2] | ((uint32_t)hu[3] << 16));
        pBl = make_uint2((uint32_t)lu[0] | ((uint32_t)lu[1] << 16),
                         (uint32_t)lu[2] | ((uint32_t)lu[3] << 16));
    };
    auto store_stage = [&](int dst, const uint4& pAh, const uint4& pAl,
                           const uint2& pBh, const uint2& pBl) {
        *(uint4*)(Ahi[dst] + arow * 24 + ahalf * 8) = pAh;
        *(uint4*)(Alo[dst] + arow * 24 + ahalf * 8) = pAl;
        *(uint2*)(Bhi[dst] + px * 24 + qd * 4) = pBh;
        *(uint2*)(Blo[dst] + px * 24 + qd * 4) = pBl;
    };

    {
        uint4 a0, a1; uint2 b0, b1;
        prefetch(0, a0, a1, b0, b1);
        store_stage(0, a0, a1, b0, b1);
    }
    __syncthreads();

    int s = 0;
    for (int it = 0; it < NIT; ++it) {
        uint4 pAh, pAl; uint2 pBh, pBl;
        const bool has_next = (it + 1 < NIT);
        if (has_next) prefetch(it + 1, pAh, pAl, pBh, pBl);

        uint32_t fAh[2][4], fAl[2][4];
        ldm_x4(fAh[0], aHiS[s]);
        ldm_x4(fAh[1], aHiS[s] + 16 * 48);
        ldm_x4(fAl[0], aLoS[s]);
        ldm_x4(fAl[1], aLoS[s] + 16 * 48);

#pragma unroll
        for (int pt = 0; pt < 2; ++pt) {
            uint32_t fBh[4], fBl[4];
            const uint32_t boff = (uint32_t)((nq * 32 + pt * 16) * 48);
            ldm_x4(fBh, bHiS[s] + boff);
            ldm_x4(fBl, bLoS[s] + boff);
#pragma unroll
            for (int f = 0; f < 2; ++f) {
                float* a0p = acc[f * 4 + pt * 2];
                float* a1p = acc[f * 4 + pt * 2 + 1];
                mma_bf16(a0p, fAh[f], fBh[0], fBh[1]);
                mma_bf16(a0p, fAh[f], fBl[0], fBl[1]);
                mma_bf16(a0p, fAl[f], fBh[0], fBh[1]);
                mma_bf16(a1p, fAh[f], fBh[2], fBh[3]);
                mma_bf16(a1p, fAh[f], fBl[2], fBl[3]);
                mma_bf16(a1p, fAl[f], fBh[2], fBh[3]);
            }
        }

        if (has_next) store_stage(s ^ 1, pAh, pAl, pBh, pBl);
        __syncthreads();
        s ^= 1;
    }

    // ---- epilogue ----
    const int r = lid >> 2;
    const int q = lid & 3;
#pragma unroll
    for (int f = 0; f < 2; ++f) {
        const int oA = m0 + f * 16 + r;
        const int oB = oA + 8;
        const float bvA = __ldg(bias + oA);
        const float bvB = __ldg(bias + oB);
        float* baseA = out + ((size_t)(bimg * OO + oA)) * HW + p0 + nq * 32 + 2 * q;
        float* baseB = out + ((size_t)(bimg * OO + oB)) * HW + p0 + nq * 32 + 2 * q;
#pragma unroll
        for (int pt = 0; pt < 2; ++pt) {
#pragma unroll
            for (int n8 = 0; n8 < 2; ++n8) {
                const int ai = f * 4 + pt * 2 + n8;
                const int col = pt * 16 + n8 * 8;
                float2 rA, rB;
                rA.x = acc[ai][0] + bvA; rA.y = acc[ai][1] + bvA;
                rB.x = acc[ai][2] + bvB; rB.y = acc[ai][3] + bvB;
                *(float2*)(baseA + col) = rA;
                *(float2*)(baseB + col) = rB;
            }
        }
    }
}

// ============================================================================
extern "C" void kernel_launch(void* const* d_in, const int* in_sizes, int n_in,
                              void* d_out, int out_size) {
    const float* x      = (const float*)d_in[0];   // (8,128,64,64)
    const float* w_om   = (const float*)d_in[1];   // (27,128,3,3)
    const float* b_om   = (const float*)d_in[2];   // (27,)
    const float* weight = (const float*)d_in[3];   // (128,128,3,3)
    const float* bias   = (const float*)d_in[4];   // (128,)
    float* out = (float*)d_out;                    // (8,128,64,64)

    prep_w<<<(OO * CKK + 255) / 256, 256>>>(weight);
    prep_wom<<<(OMM * CKK + 255) / 256, 256>>>(w_om);
    om_gemm<<<NPIX / 128, 256>>>(x);
    om_final<<<NPIX / 256, 256>>>(b_om);
    gemm_mma<<<NPIX / 64, 256>>>(x, bias, out);
}

// round 16
// speedup vs baseline: 1.5841x; 1.5841x over previous
#include <cuda_runtime.h>
#include <cuda_bf16.h>
#include <cstdint>
#include <math.h>

#define BB   8
#define CC   128
#define OO   128
#define HH   64
#define WW   64
#define HW   4096
#define NPIX 32768
#define CKK  1152
#define NOM  27
#define OMM  32                // padded M for om GEMM

// ---------------- device scratch (allocation-free rule) ----------------
__device__ __align__(16) unsigned short g_Wph[OO * CKK];
__device__ __align__(16) unsigned short g_Wpl[OO * CKK];
__device__ __align__(16) unsigned short g_WomH[OMM * CKK];
__device__ __align__(16) unsigned short g_WomL[OMM * CKK];
__device__ float   g_om[NOM * NPIX];
__device__ float4  g_w4[BB * 9 * HW];
__device__ ushort4 g_idx[BB * 9 * HW];

// ============================================================================
// common helpers
// ============================================================================
__device__ __forceinline__ uint32_t smem_u32(const void* p) {
    uint32_t a;
    asm("{ .reg .u64 t; cvta.to.shared.u64 t, %1; cvt.u32.u64 %0, t; }" : "=r"(a) : "l"(p));
    return a;
}
__device__ __forceinline__ void ldm_x4(uint32_t* r, uint32_t addr) {
    asm volatile("ldmatrix.sync.aligned.m8n8.x4.shared.b16 {%0,%1,%2,%3}, [%4];"
                 : "=r"(r[0]), "=r"(r[1]), "=r"(r[2]), "=r"(r[3]) : "r"(addr));
}
__device__ __forceinline__ void mma_bf16(float* c, const uint32_t* a, uint32_t b0, uint32_t b1) {
    asm volatile("mma.sync.aligned.m16n8k16.row.col.f32.bf16.bf16.f32 "
                 "{%0,%1,%2,%3}, {%4,%5,%6,%7}, {%8,%9}, {%0,%1,%2,%3};"
                 : "+f"(c[0]), "+f"(c[1]), "+f"(c[2]), "+f"(c[3])
                 : "r"(a[0]), "r"(a[1]), "r"(a[2]), "r"(a[3]), "r"(b0), "r"(b1));
}
__device__ __forceinline__ void bf16_split(float v, unsigned short& h, unsigned short& l) {
    const __nv_bfloat16 hb = __float2bfloat16(v);
    h = __bfloat16_as_ushort(hb);
    l = __bfloat16_as_ushort(__float2bfloat16(v - __bfloat162float(hb)));
}

// ============================================================================
// Kernel 0a/0b: weight permute + bf16 hi/lo split (unchanged)
// ============================================================================
__global__ __launch_bounds__(256)
void prep_w(const float* __restrict__ w) {
    const int i = blockIdx.x * 256 + threadIdx.x;
    if (i < OO * CKK) {
        const int o = i / CKK;
        const int kk = i - o * CKK;
        const int k = kk >> 7;
        const int c = kk & 127;
        unsigned short h, l;
        bf16_split(w[(size_t)o * CKK + c * 9 + k], h, l);
        g_Wph[i] = h; g_Wpl[i] = l;
    }
}
__global__ __launch_bounds__(256)
void prep_wom(const float* __restrict__ w_om) {
    const int i = blockIdx.x * 256 + threadIdx.x;
    if (i < OMM * CKK) {
        const int o = i / CKK;
        const int kk = i - o * CKK;
        const int t = kk >> 7;
        const int c = kk & 127;
        const float v = (o < NOM) ? w_om[(size_t)o * CKK + c * 9 + t] : 0.f;
        unsigned short h, l;
        bf16_split(v, h, l);
        g_WomH[i] = h; g_WomL[i] = l;
    }
}

// ============================================================================
// Kernel 1a: om conv as bf16 tensor GEMM — NEW 64px tile, grid 512.
// 32 o x 64 px per CTA; warp grid 2(m) x 4(n), acc = 8 regs -> high occupancy.
// ============================================================================
#define BKC  16
#define BSTU 24
#define NIT  (CKK / BKC)        // 72

__global__ __launch_bounds__(256)
void om_gemm(const float* __restrict__ x) {
    __shared__ __align__(16) unsigned short OAh[2][OMM * BSTU];
    __shared__ __align__(16) unsigned short OAl[2][OMM * BSTU];
    __shared__ __align__(16) unsigned short OBh[2][64 * BSTU];
    __shared__ __align__(16) unsigned short OBl[2][64 * BSTU];

    const int tid = threadIdx.x;
    const int wid = tid >> 5;
    const int lid = tid & 31;
    const int bp0 = blockIdx.x * 64;

    const int bimg = bp0 >> 12;
    const int p0 = bp0 & 4095;
    const float* __restrict__ xbase = x + (size_t)(bimg * CC) * HW;

    // producers: A = 32 rows x 16 kk (tid<64); B = 64 px x 4 c-quads
    const int arow = tid >> 1;
    const int ahalf = tid & 1;
    const int px = tid & 63;
    const int qd = tid >> 6;            // 0..3, 4 channels each
    const int pj = p0 + px;
    const int y = pj >> 6;
    const int xx = pj & 63;

    // consumers: 2(m) x 4(n) warps, each 16 o x 16 px
    const int mid = wid >> 2;           // 0..1
    const int nq = wid & 3;             // 0..3
    const int m0 = mid * 16;
    const uint32_t aOff =
        (uint32_t)((m0 + (lid & 7) + ((lid >> 3) & 1) * 8) * 48 + ((lid >> 4) & 1) * 16);
    const uint32_t bOff =
        (uint32_t)((nq * 16 + (lid & 7) + ((lid >> 4) & 1) * 8) * 48 + ((lid >> 3) & 1) * 16);
    const uint32_t aHiS[2] = { smem_u32(OAh[0]) + aOff, smem_u32(OAh[1]) + aOff };
    const uint32_t aLoS[2] = { smem_u32(OAl[0]) + aOff, smem_u32(OAl[1]) + aOff };
    const uint32_t bHiS[2] = { smem_u32(OBh[0]) + bOff, smem_u32(OBh[1]) + bOff };
    const uint32_t bLoS[2] = { smem_u32(OBl[0]) + bOff, smem_u32(OBl[1]) + bOff };

    float acc[2][4];
#pragma unroll
    for (int i = 0; i < 2; ++i)
#pragma unroll
        for (int j = 0; j < 4; ++j) acc[i][j] = 0.f;

    auto prefetch = [&](int j, uint4& pAh, uint4& pAl, uint2& pBh, uint2& pBl) {
        const int ck0 = j * BKC;
        if (tid < 64) {
            const size_t gi = (size_t)arow * CKK + ck0 + ahalf * 8;
            pAh = *(const uint4*)(g_WomH + gi);
            pAl = *(const uint4*)(g_WomL + gi);
        }
        const int t = j >> 3;
        const int dy = t / 3 - 1;
        const int dx = t - (t / 3) * 3 - 1;
        const int yy = y + dy;
        const int xxx = xx + dx;
        const bool ok = (yy >= 0) & (yy < HH) & (xxx >= 0) & (xxx < WW);
        const int off = ok ? yy * WW + xxx : 0;
        const int cbase = ((j & 7) * 16) + qd * 4;
        const float* __restrict__ xc = xbase + (size_t)cbase * HW + off;
        unsigned short hu[4], lu[4];
#pragma unroll
        for (int j2 = 0; j2 < 4; ++j2) {
            const float v = ok ? __ldg(xc) : 0.f;
            bf16_split(v, hu[j2], lu[j2]);
            xc += HW;
        }
        pBh = make_uint2((uint32_t)hu[0] | ((uint32_t)hu[1] << 16),
                         (uint32_t)hu[2] | ((uint32_t)hu[3] << 16));
        pBl = make_uint2((uint32_t)lu[0] | ((uint32_t)lu[1] << 16),
                         (uint32_t)lu[2] | ((uint32_t)lu[3] << 16));
    };
    auto store_stage = [&](int dst, const uint4& pAh, const uint4& pAl,
                           const uint2& pBh, const uint2& pBl) {
        if (tid < 64) {
            *(uint4*)(OAh[dst] + arow * BSTU + ahalf * 8) = pAh;
            *(uint4*)(OAl[dst] + arow * BSTU + ahalf * 8) = pAl;
        }
        *(uint2*)(OBh[dst] + px * BSTU + qd * 4) = pBh;
        *(uint2*)(OBl[dst] + px * BSTU + qd * 4) = pBl;
    };

    {
        uint4 a0, a1; uint2 b0, b1;
        prefetch(0, a0, a1, b0, b1);
        store_stage(0, a0, a1, b0, b1);
    }
    __syncthreads();

    int s = 0;
    for (int it = 0; it < NIT; ++it) {
        uint4 pAh, pAl; uint2 pBh, pBl;
        const bool has_next = (it + 1 < NIT);
        if (has_next) prefetch(it + 1, pAh, pAl, pBh, pBl);

        uint32_t fAh[4], fAl[4], fBh[4], fBl[4];
        ldm_x4(fAh, aHiS[s]);
        ldm_x4(fAl, aLoS[s]);
        ldm_x4(fBh, bHiS[s]);
        ldm_x4(fBl, bLoS[s]);

        mma_bf16(acc[0], fAh, fBh[0], fBh[1]);
        mma_bf16(acc[0], fAh, fBl[0], fBl[1]);
        mma_bf16(acc[0], fAl, fBh[0], fBh[1]);
        mma_bf16(acc[1], fAh, fBh[2], fBh[3]);
        mma_bf16(acc[1], fAh, fBl[2], fBl[3]);
        mma_bf16(acc[1], fAl, fBh[2], fBh[3]);

        if (has_next) store_stage(s ^ 1, pAh, pAl, pBh, pBl);
        __syncthreads();
        s ^= 1;
    }

    // epilogue: write fp32 rows o<27 to g_om
    const int r = lid >> 2;
    const int q = lid & 3;
    const int oA = m0 + r;
    const int oB = m0 + r + 8;
#pragma unroll
    for (int nt = 0; nt < 2; ++nt) {
        const int col = nq * 16 + nt * 8 + 2 * q;
        if (oA < NOM)
            *(float2*)(g_om + (size_t)oA * NPIX + bp0 + col) = make_float2(acc[nt][0], acc[nt][1]);
        if (oB < NOM)
            *(float2*)(g_om + (size_t)oB * NPIX + bp0 + col) = make_float2(acc[nt][2], acc[nt][3]);
    }
}

// ============================================================================
// Kernel 1b: add bias, softmax mask, bilinear weights + offsets (unchanged)
// ============================================================================
__global__ __launch_bounds__(256)
void om_final(const float* __restrict__ b_om) {
    const int bp = blockIdx.x * 256 + threadIdx.x;
    const int b = bp >> 12;
    const int p = bp & 4095;
    const int y = p >> 6;
    const int xx = p & 63;

    float acc[NOM];
#pragma unroll
    for (int oc = 0; oc < NOM; ++oc)
        acc[oc] = __ldg(b_om + oc) + g_om[(size_t)oc * NPIX + bp];

    float mx = acc[18];
#pragma unroll
    for (int k = 1; k < 9; ++k) mx = fmaxf(mx, acc[18 + k]);
    float e[9], s = 0.f;
#pragma unroll
    for (int k = 0; k < 9; ++k) { e[k] = expf(acc[18 + k] - mx); s += e[k]; }
    const float inv = 1.f / s;

#pragma unroll
    for (int k = 0; k < 9; ++k) {
        const float m = e[k] * inv;
        const float py = (float)(y - 1 + k / 3) + acc[2 * k];
        const float px = (float)(xx - 1 + k % 3) + acc[2 * k + 1];
        const float fy = floorf(py), fx = floorf(px);
        const int y0 = (int)fy, x0 = (int)fx;
        const float wy1 = py - fy, wx1 = px - fx;
        const float wy0 = 1.f - wy1, wx0 = 1.f - wx1;
        const bool vy0 = (y0 >= 0) & (y0 < HH);
        const bool vy1 = (y0 >= -1) & (y0 < HH - 1);
        const bool vx0 = (x0 >= 0) & (x0 < WW);
        const bool vx1 = (x0 >= -1) & (x0 < WW - 1);
        float4 w4;
        w4.x = (vy0 & vx0) ? wy0 * wx0 * m : 0.f;
        w4.y = (vy0 & vx1) ? wy0 * wx1 * m : 0.f;
        w4.z = (vy1 & vx0) ? wy1 * wx0 * m : 0.f;
        w4.w = (vy1 & vx1) ? wy1 * wx1 * m : 0.f;
        const int y0c = min(max(y0, 0), HH - 1);
        const int y1c = min(max(y0 + 1, 0), HH - 1);
        const int x0c = min(max(x0, 0), WW - 1);
        const int x1c = min(max(x0 + 1, 0), WW - 1);
        ushort4 s4;
        s4.x = (unsigned short)(y0c * WW + x0c);
        s4.y = (unsigned short)(y0c * WW + x1c);
        s4.z = (unsigned short)(y1c * WW + x0c);
        s4.w = (unsigned short)(y1c * WW + x1c);
        const int idx = (b * 9 + k) * HW + p;
        g_w4[idx] = w4;
        g_idx[idx] = s4;
    }
}

// ============================================================================
// Kernel 2: main bf16 split GEMM — EXACT R11 version (best known: 157us).
// 128 o x 128 px per CTA, 4(m) x 2(n) warps, 2 CTAs/SM, register prefetch.
// ============================================================================
#define STGU (128 * BSTU)

__global__ __launch_bounds__(256, 2)
void gemm_mma(const float* __restrict__ x, const float* __restrict__ bias,
              float* __restrict__ out) {
    __shared__ __align__(16) unsigned short Ahi[2][STGU];
    __shared__ __align__(16) unsigned short Alo[2][STGU];
    __shared__ __align__(16) unsigned short Bhi[2][STGU];
    __shared__ __align__(16) unsigned short Blo[2][STGU];

    const int tid = threadIdx.x;
    const int wid = tid >> 5;
    const int lid = tid & 31;
    const int n0 = blockIdx.x * 128;

    const int bimg = n0 >> 12;
    const int p0 = n0 & 4095;
    const int bimg9 = bimg * 9;
    const float* __restrict__ xb = x + (size_t)(bimg * CC) * HW;

    const int arow = tid >> 1;
    const int ahalf = tid & 1;
    const int px = tid & 127;
    const int bh = tid >> 7;
    const int pj = p0 + px;

    const int mid = wid >> 1;           // 0..3
    const int nq = wid & 1;             // 0..1
    const int m0 = mid * 32;
    const uint32_t aOff =
        (uint32_t)((m0 + (lid & 7) + ((lid >> 3) & 1) * 8) * 48 + ((lid >> 4) & 1) * 16);
    const uint32_t bOff =
        (uint32_t)(((lid & 7) + ((lid >> 4) & 1) * 8) * 48 + ((lid >> 3) & 1) * 16);
    const uint32_t aHiS[2] = { smem_u32(Ahi[0]) + aOff, smem_u32(Ahi[1]) + aOff };
    const uint32_t aLoS[2] = { smem_u32(Alo[0]) + aOff, smem_u32(Alo[1]) + aOff };
    const uint32_t bHiS[2] = { smem_u32(Bhi[0]) + bOff, smem_u32(Bhi[1]) + bOff };
    const uint32_t bLoS[2] = { smem_u32(Blo[0]) + bOff, smem_u32(Blo[1]) + bOff };

    float acc[16][4];
#pragma unroll
    for (int i = 0; i < 16; ++i)
#pragma unroll
        for (int j = 0; j < 4; ++j) acc[i][j] = 0.f;

    int kcur = -1;
    float4 cw4;
    ushort4 cidx;

    auto prefetch = [&](int j, uint4& pAh, uint4& pAl, uint4& pBh, uint4& pBl) {
        const int ck0 = j * BKC;
        const size_t gi = (size_t)arow * CKK + ck0 + ahalf * 8;
        pAh = *(const uint4*)(g_Wph + gi);
        pAl = *(const uint4*)(g_Wpl + gi);

        const int kn = j >> 3;
        if (kn != kcur) {
            kcur = kn;
            const int t = (bimg9 + kn) * HW + pj;
            cw4 = __ldg(&g_w4[t]);
            cidx = __ldg(&g_idx[t]);
        }
        const int cbase = ((j & 7) * 16) + bh * 8;
        const float* __restrict__ xc = xb + (size_t)cbase * HW;
        unsigned short hu[8], lu[8];
#pragma unroll
        for (int j2 = 0; j2 < 8; ++j2) {
            const float v = cw4.x * __ldg(xc + cidx.x) + cw4.y * __ldg(xc + cidx.y)
                          + cw4.z * __ldg(xc + cidx.z) + cw4.w * __ldg(xc + cidx.w);
            bf16_split(v, hu[j2], lu[j2]);
            xc += HW;
        }
        pBh = make_uint4((uint32_t)hu[0] | ((uint32_t)hu[1] << 16),
                         (uint32_t)hu[2] | ((uint32_t)hu[3] << 16),
                         (uint32_t)hu[4] | ((uint32_t)hu[5] << 16),
                         (uint32_t)hu[6] | ((uint32_t)hu[7] << 16));
        pBl = make_uint4((uint32_t)lu[0] | ((uint32_t)lu[1] << 16),
                         (uint32_t)lu[2] | ((uint32_t)lu[3] << 16),
                         (uint32_t)lu[4] | ((uint32_t)lu[5] << 16),
                         (uint32_t)lu[6] | ((uint32_t)lu[7] << 16));
    };
    auto store_stage = [&](int dst, const uint4& pAh, const uint4& pAl,
                           const uint4& pBh, const uint4& pBl) {
        *(uint4*)(Ahi[dst] + arow * BSTU + ahalf * 8) = pAh;
        *(uint4*)(Alo[dst] + arow * BSTU + ahalf * 8) = pAl;
        *(uint4*)(Bhi[dst] + px * BSTU + bh * 8) = pBh;
        *(uint4*)(Blo[dst] + px * BSTU + bh * 8) = pBl;
    };

    {
        uint4 a0, a1, b0, b1;
        prefetch(0, a0, a1, b0, b1);
        store_stage(0, a0, a1, b0, b1);
    }
    __syncthreads();

    int s = 0;
    for (int it = 0; it < NIT; ++it) {
        uint4 pAh, pAl, pBh, pBl;
        const bool has_next = (it + 1 < NIT);
        if (has_next) prefetch(it + 1, pAh, pAl, pBh, pBl);

        uint32_t fAh[2][4], fAl[2][4];
        ldm_x4(fAh[0], aHiS[s]);
        ldm_x4(fAh[1], aHiS[s] + 16 * 48);
        ldm_x4(fAl[0], aLoS[s]);
        ldm_x4(fAl[1], aLoS[s] + 16 * 48);

#pragma unroll
        for (int pt = 0; pt < 4; ++pt) {
            uint32_t fBh[4], fBl[4];
            const uint32_t boff = (uint32_t)((nq * 64 + pt * 16) * 48);
            ldm_x4(fBh, bHiS[s] + boff);
            ldm_x4(fBl, bLoS[s] + boff);
#pragma unroll
            for (int f = 0; f < 2; ++f) {
                mma_bf16(acc[f * 8 + 2 * pt], fAh[f], fBh[0], fBh[1]);
                mma_bf16(acc[f * 8 + 2 * pt], fAh[f], fBl[0], fBl[1]);
                mma_bf16(acc[f * 8 + 2 * pt], fAl[f], fBh[0], fBh[1]);
                mma_bf16(acc[f * 8 + 2 * pt + 1], fAh[f], fBh[2], fBh[3]);
                mma_bf16(acc[f * 8 + 2 * pt + 1], fAh[f], fBl[2], fBl[3]);
                mma_bf16(acc[f * 8 + 2 * pt + 1], fAl[f], fBh[2], fBh[3]);
            }
        }

        if (has_next) store_stage(s ^ 1, pAh, pAl, pBh, pBl);
        __syncthreads();
        s ^= 1;
    }

    // ---- epilogue ----
    const int r = lid >> 2;
    const int q = lid & 3;
#pragma unroll
    for (int f = 0; f < 2; ++f) {
        const int oA = m0 + f * 16 + r;
        const int oB = oA + 8;
        const float bvA = __ldg(bias + oA);
        const float bvB = __ldg(bias + oB);
        float* baseA = out + ((size_t)(bimg * OO + oA)) * HW + p0 + nq * 64 + 2 * q;
        float* baseB = out + ((size_t)(bimg * OO + oB)) * HW + p0 + nq * 64 + 2 * q;
#pragma unroll
        for (int nt = 0; nt < 8; ++nt) {
            const int ai = f * 8 + nt;
            float2 rA, rB;
            rA.x = acc[ai][0] + bvA; rA.y = acc[ai][1] + bvA;
            rB.x = acc[ai][2] + bvB; rB.y = acc[ai][3] + bvB;
            *(float2*)(baseA + nt * 8) = rA;
            *(float2*)(baseB + nt * 8) = rB;
        }
    }
}

// ============================================================================
extern "C" void kernel_launch(void* const* d_in, const int* in_sizes, int n_in,
                              void* d_out, int out_size) {
    const float* x      = (const float*)d_in[0];   // (8,128,64,64)
    const float* w_om   = (const float*)d_in[1];   // (27,128,3,3)
    const float* b_om   = (const float*)d_in[2];   // (27,)
    const float* weight = (const float*)d_in[3];   // (128,128,3,3)
    const float* bias   = (const float*)d_in[4];   // (128,)
    float* out = (float*)d_out;                    // (8,128,64,64)

    prep_w<<<(OO * CKK + 255) / 256, 256>>>(weight);
    prep_wom<<<(OMM * CKK + 255) / 256, 256>>>(w_om);
    om_gemm<<<NPIX / 64, 256>>>(x);
    om_final<<<NPIX / 256, 256>>>(b_om);
    gemm_mma<<<NPIX / 128, 256>>>(x, bias, out);
}

// round 17
// speedup vs baseline: 1.6126x; 1.0180x over previous
#include <cuda_runtime.h>
#include <cuda_bf16.h>
#include <cstdint>
#include <math.h>

#define BB   8
#define CC   128
#define OO   128
#define HH   64
#define WW   64
#define HW   4096
#define NPIX 32768
#define CKK  1152
#define NOM  27
#define OMM  32                // padded M for om GEMM

// ---------------- device scratch (allocation-free rule) ----------------
__device__ __align__(16) unsigned short g_Wph[OO * CKK];
__device__ __align__(16) unsigned short g_Wpl[OO * CKK];
__device__ __align__(16) unsigned short g_WomH[OMM * CKK];
__device__ __align__(16) unsigned short g_WomL[OMM * CKK];
__device__ float4  g_w4[BB * 9 * HW];
__device__ ushort4 g_idx[BB * 9 * HW];

// ============================================================================
// common helpers
// ============================================================================
__device__ __forceinline__ uint32_t smem_u32(const void* p) {
    uint32_t a;
    asm("{ .reg .u64 t; cvta.to.shared.u64 t, %1; cvt.u32.u64 %0, t; }" : "=r"(a) : "l"(p));
    return a;
}
__device__ __forceinline__ void ldm_x4(uint32_t* r, uint32_t addr) {
    asm volatile("ldmatrix.sync.aligned.m8n8.x4.shared.b16 {%0,%1,%2,%3}, [%4];"
                 : "=r"(r[0]), "=r"(r[1]), "=r"(r[2]), "=r"(r[3]) : "r"(addr));
}
__device__ __forceinline__ void mma_bf16(float* c, const uint32_t* a, uint32_t b0, uint32_t b1) {
    asm volatile("mma.sync.aligned.m16n8k16.row.col.f32.bf16.bf16.f32 "
                 "{%0,%1,%2,%3}, {%4,%5,%6,%7}, {%8,%9}, {%0,%1,%2,%3};"
                 : "+f"(c[0]), "+f"(c[1]), "+f"(c[2]), "+f"(c[3])
                 : "r"(a[0]), "r"(a[1]), "r"(a[2]), "r"(a[3]), "r"(b0), "r"(b1));
}
__device__ __forceinline__ void bf16_split(float v, unsigned short& h, unsigned short& l) {
    const __nv_bfloat16 hb = __float2bfloat16(v);
    h = __bfloat16_as_ushort(hb);
    l = __bfloat16_as_ushort(__float2bfloat16(v - __bfloat162float(hb)));
}

// ============================================================================
// Kernel 0: merged weight permute + bf16 hi/lo split (main + om weights)
// ============================================================================
__global__ __launch_bounds__(256)
void prep_all(const float* __restrict__ w, const float* __restrict__ w_om) {
    const int i = blockIdx.x * 256 + threadIdx.x;
    if (i < OO * CKK) {
        const int o = i / CKK;
        const int kk = i - o * CKK;
        const int k = kk >> 7;
        const int c = kk & 127;
        unsigned short h, l;
        bf16_split(w[(size_t)o * CKK + c * 9 + k], h, l);
        g_Wph[i] = h; g_Wpl[i] = l;
    } else {
        const int j = i - OO * CKK;
        if (j < OMM * CKK) {
            const int o = j / CKK;
            const int kk = j - o * CKK;
            const int t = kk >> 7;
            const int c = kk & 127;
            const float v = (o < NOM) ? w_om[(size_t)o * CKK + c * 9 + t] : 0.f;
            unsigned short h, l;
            bf16_split(v, h, l);
            g_WomH[j] = h; g_WomL[j] = l;
        }
    }
}

// ============================================================================
// Kernel 1: om conv as bf16 tensor GEMM (32o x 64px tile, grid 512) with
// FUSED om_final epilogue: the CTA's M tile covers all 27 channels, so after
// the K loop it holds the full om vector per pixel -> smem transpose, then
// 64 threads do bias+softmax+bilinear-weight emit directly.
// ============================================================================
#define BKC  16
#define BSTU 24
#define NIT  (CKK / BKC)        // 72

__global__ __launch_bounds__(256)
void om_gemm(const float* __restrict__ x, const float* __restrict__ b_om) {
    __shared__ __align__(16) unsigned short OAh[2][OMM * BSTU];
    __shared__ __align__(16) unsigned short OAl[2][OMM * BSTU];
    __shared__ __align__(16) unsigned short OBh[2][64 * BSTU];
    __shared__ __align__(16) unsigned short OBl[2][64 * BSTU];
    __shared__ float som[OMM][64];   // om result transpose buffer

    const int tid = threadIdx.x;
    const int wid = tid >> 5;
    const int lid = tid & 31;
    const int bp0 = blockIdx.x * 64;

    const int bimg = bp0 >> 12;
    const int p0 = bp0 & 4095;
    const float* __restrict__ xbase = x + (size_t)(bimg * CC) * HW;

    // producers: A = 32 rows x 16 kk (tid<64); B = 64 px x 4 c-quads
    const int arow = tid >> 1;
    const int ahalf = tid & 1;
    const int px = tid & 63;
    const int qd = tid >> 6;            // 0..3, 4 channels each
    const int pj = p0 + px;
    const int y = pj >> 6;
    const int xx = pj & 63;

    // consumers: 2(m) x 4(n) warps, each 16 o x 16 px
    const int mid = wid >> 2;           // 0..1
    const int nq = wid & 3;             // 0..3
    const int m0 = mid * 16;
    const uint32_t aOff =
        (uint32_t)((m0 + (lid & 7) + ((lid >> 3) & 1) * 8) * 48 + ((lid >> 4) & 1) * 16);
    const uint32_t bOff =
        (uint32_t)((nq * 16 + (lid & 7) + ((lid >> 4) & 1) * 8) * 48 + ((lid >> 3) & 1) * 16);
    const uint32_t aHiS[2] = { smem_u32(OAh[0]) + aOff, smem_u32(OAh[1]) + aOff };
    const uint32_t aLoS[2] = { smem_u32(OAl[0]) + aOff, smem_u32(OAl[1]) + aOff };
    const uint32_t bHiS[2] = { smem_u32(OBh[0]) + bOff, smem_u32(OBh[1]) + bOff };
    const uint32_t bLoS[2] = { smem_u32(OBl[0]) + bOff, smem_u32(OBl[1]) + bOff };

    float acc[2][4];
#pragma unroll
    for (int i = 0; i < 2; ++i)
#pragma unroll
        for (int j = 0; j < 4; ++j) acc[i][j] = 0.f;

    auto prefetch = [&](int j, uint4& pAh, uint4& pAl, uint2& pBh, uint2& pBl) {
        const int ck0 = j * BKC;
        if (tid < 64) {
            const size_t gi = (size_t)arow * CKK + ck0 + ahalf * 8;
            pAh = *(const uint4*)(g_WomH + gi);
            pAl = *(const uint4*)(g_WomL + gi);
        }
        const int t = j >> 3;
        const int dy = t / 3 - 1;
        const int dx = t - (t / 3) * 3 - 1;
        const int yy = y + dy;
        const int xxx = xx + dx;
        const bool ok = (yy >= 0) & (yy < HH) & (xxx >= 0) & (xxx < WW);
        const int off = ok ? yy * WW + xxx : 0;
        const int cbase = ((j & 7) * 16) + qd * 4;
        const float* __restrict__ xc = xbase + (size_t)cbase * HW + off;
        unsigned short hu[4], lu[4];
#pragma unroll
        for (int j2 = 0; j2 < 4; ++j2) {
            const float v = ok ? __ldg(xc) : 0.f;
            bf16_split(v, hu[j2], lu[j2]);
            xc += HW;
        }
        pBh = make_uint2((uint32_t)hu[0] | ((uint32_t)hu[1] << 16),
                         (uint32_t)hu[2] | ((uint32_t)hu[3] << 16));
        pBl = make_uint2((uint32_t)lu[0] | ((uint32_t)lu[1] << 16),
                         (uint32_t)lu[2] | ((uint32_t)lu[3] << 16));
    };
    auto store_stage = [&](int dst, const uint4& pAh, const uint4& pAl,
                           const uint2& pBh, const uint2& pBl) {
        if (tid < 64) {
            *(uint4*)(OAh[dst] + arow * BSTU + ahalf * 8) = pAh;
            *(uint4*)(OAl[dst] + arow * BSTU + ahalf * 8) = pAl;
        }
        *(uint2*)(OBh[dst] + px * BSTU + qd * 4) = pBh;
        *(uint2*)(OBl[dst] + px * BSTU + qd * 4) = pBl;
    };

    {
        uint4 a0, a1; uint2 b0, b1;
        prefetch(0, a0, a1, b0, b1);
        store_stage(0, a0, a1, b0, b1);
    }
    __syncthreads();

    int s = 0;
    for (int it = 0; it < NIT; ++it) {
        uint4 pAh, pAl; uint2 pBh, pBl;
        const bool has_next = (it + 1 < NIT);
        if (has_next) prefetch(it + 1, pAh, pAl, pBh, pBl);

        uint32_t fAh[4], fAl[4], fBh[4], fBl[4];
        ldm_x4(fAh, aHiS[s]);
        ldm_x4(fAl, aLoS[s]);
        ldm_x4(fBh, bHiS[s]);
        ldm_x4(fBl, bLoS[s]);

        mma_bf16(acc[0], fAh, fBh[0], fBh[1]);
        mma_bf16(acc[0], fAh, fBl[0], fBl[1]);
        mma_bf16(acc[0], fAl, fBh[0], fBh[1]);
        mma_bf16(acc[1], fAh, fBh[2], fBh[3]);
        mma_bf16(acc[1], fAh, fBl[2], fBl[3]);
        mma_bf16(acc[1], fAl, fBh[2], fBh[3]);

        if (has_next) store_stage(s ^ 1, pAh, pAl, pBh, pBl);
        __syncthreads();
        s ^= 1;
    }

    // ---- fused epilogue: transpose to smem, then om_final per pixel ----
    {
        const int r = lid >> 2;
        const int q = lid & 3;
        const int oA = m0 + r;
        const int oB = m0 + r + 8;
#pragma unroll
        for (int nt = 0; nt < 2; ++nt) {
            const int col = nq * 16 + nt * 8 + 2 * q;
            som[oA][col] = acc[nt][0];
            som[oA][col + 1] = acc[nt][1];
            som[oB][col] = acc[nt][2];
            som[oB][col + 1] = acc[nt][3];
        }
    }
    __syncthreads();

    if (tid < 64) {
        const int p = p0 + tid;           // pixel within image (tile is image-local)
        const int py_ = p >> 6;
        const int px_ = p & 63;

        float accv[NOM];
#pragma unroll
        for (int oc = 0; oc < NOM; ++oc)
            accv[oc] = som[oc][tid] + __ldg(b_om + oc);

        float mx = accv[18];
#pragma unroll
        for (int k = 1; k < 9; ++k) mx = fmaxf(mx, accv[18 + k]);
        float e[9], ssum = 0.f;
#pragma unroll
        for (int k = 0; k < 9; ++k) { e[k] = expf(accv[18 + k] - mx); ssum += e[k]; }
        const float inv = 1.f / ssum;

#pragma unroll
        for (int k = 0; k < 9; ++k) {
            const float m = e[k] * inv;
            const float py = (float)(py_ - 1 + k / 3) + accv[2 * k];
            const float pxf = (float)(px_ - 1 + k % 3) + accv[2 * k + 1];
            const float fy = floorf(py), fx = floorf(pxf);
            const int y0 = (int)fy, x0 = (int)fx;
            const float wy1 = py - fy, wx1 = pxf - fx;
            const float wy0 = 1.f - wy1, wx0 = 1.f - wx1;
            const bool vy0 = (y0 >= 0) & (y0 < HH);
            const bool vy1 = (y0 >= -1) & (y0 < HH - 1);
            const bool vx0 = (x0 >= 0) & (x0 < WW);
            const bool vx1 = (x0 >= -1) & (x0 < WW - 1);
            float4 w4;
            w4.x = (vy0 & vx0) ? wy0 * wx0 * m : 0.f;
            w4.y = (vy0 & vx1) ? wy0 * wx1 * m : 0.f;
            w4.z = (vy1 & vx0) ? wy1 * wx0 * m : 0.f;
            w4.w = (vy1 & vx1) ? wy1 * wx1 * m : 0.f;
            const int y0c = min(max(y0, 0), HH - 1);
            const int y1c = min(max(y0 + 1, 0), HH - 1);
            const int x0c = min(max(x0, 0), WW - 1);
            const int x1c = min(max(x0 + 1, 0), WW - 1);
            ushort4 s4;
            s4.x = (unsigned short)(y0c * WW + x0c);
            s4.y = (unsigned short)(y0c * WW + x1c);
            s4.z = (unsigned short)(y1c * WW + x0c);
            s4.w = (unsigned short)(y1c * WW + x1c);
            const int idx = (bimg * 9 + k) * HW + p;
            g_w4[idx] = w4;
            g_idx[idx] = s4;
        }
    }
}

// ============================================================================
// Kernel 2: main bf16 split GEMM — EXACT R11 version (best known: 157us).
// 128 o x 128 px per CTA, 4(m) x 2(n) warps, 2 CTAs/SM, register prefetch.
// ============================================================================
#define STGU (128 * BSTU)

__global__ __launch_bounds__(256, 2)
void gemm_mma(const float* __restrict__ x, const float* __restrict__ bias,
              float* __restrict__ out) {
    __shared__ __align__(16) unsigned short Ahi[2][STGU];
    __shared__ __align__(16) unsigned short Alo[2][STGU];
    __shared__ __align__(16) unsigned short Bhi[2][STGU];
    __shared__ __align__(16) unsigned short Blo[2][STGU];

    const int tid = threadIdx.x;
    const int wid = tid >> 5;
    const int lid = tid & 31;
    const int n0 = blockIdx.x * 128;

    const int bimg = n0 >> 12;
    const int p0 = n0 & 4095;
    const int bimg9 = bimg * 9;
    const float* __restrict__ xb = x + (size_t)(bimg * CC) * HW;

    const int arow = tid >> 1;
    const int ahalf = tid & 1;
    const int px = tid & 127;
    const int bh = tid >> 7;
    const int pj = p0 + px;

    const int mid = wid >> 1;           // 0..3
    const int nq = wid & 1;             // 0..1
    const int m0 = mid * 32;
    const uint32_t aOff =
        (uint32_t)((m0 + (lid & 7) + ((lid >> 3) & 1) * 8) * 48 + ((lid >> 4) & 1) * 16);
    const uint32_t bOff =
        (uint32_t)(((lid & 7) + ((lid >> 4) & 1) * 8) * 48 + ((lid >> 3) & 1) * 16);
    const uint32_t aHiS[2] = { smem_u32(Ahi[0]) + aOff, smem_u32(Ahi[1]) + aOff };
    const uint32_t aLoS[2] = { smem_u32(Alo[0]) + aOff, smem_u32(Alo[1]) + aOff };
    const uint32_t bHiS[2] = { smem_u32(Bhi[0]) + bOff, smem_u32(Bhi[1]) + bOff };
    const uint32_t bLoS[2] = { smem_u32(Blo[0]) + bOff, smem_u32(Blo[1]) + bOff };

    float acc[16][4];
#pragma unroll
    for (int i = 0; i < 16; ++i)
#pragma unroll
        for (int j = 0; j < 4; ++j) acc[i][j] = 0.f;

    int kcur = -1;
    float4 cw4;
    ushort4 cidx;

    auto prefetch = [&](int j, uint4& pAh, uint4& pAl, uint4& pBh, uint4& pBl) {
        const int ck0 = j * BKC;
        const size_t gi = (size_t)arow * CKK + ck0 + ahalf * 8;
        pAh = *(const uint4*)(g_Wph + gi);
        pAl = *(const uint4*)(g_Wpl + gi);

        const int kn = j >> 3;
        if (kn != kcur) {
            kcur = kn;
            const int t = (bimg9 + kn) * HW + pj;
            cw4 = __ldg(&g_w4[t]);
            cidx = __ldg(&g_idx[t]);
        }
        const int cbase = ((j & 7) * 16) + bh * 8;
        const float* __restrict__ xc = xb + (size_t)cbase * HW;
        unsigned short hu[8], lu[8];
#pragma unroll
        for (int j2 = 0; j2 < 8; ++j2) {
            const float v = cw4.x * __ldg(xc + cidx.x) + cw4.y * __ldg(xc + cidx.y)
                          + cw4.z * __ldg(xc + cidx.z) + cw4.w * __ldg(xc + cidx.w);
            bf16_split(v, hu[j2], lu[j2]);
            xc += HW;
        }
        pBh = make_uint4((uint32_t)hu[0] | ((uint32_t)hu[1] << 16),
                         (uint32_t)hu[2] | ((uint32_t)hu[3] << 16),
                         (uint32_t)hu[4] | ((uint32_t)hu[5] << 16),
                         (uint32_t)hu[6] | ((uint32_t)hu[7] << 16));
        pBl = make_uint4((uint32_t)lu[0] | ((uint32_t)lu[1] << 16),
                         (uint32_t)lu[2] | ((uint32_t)lu[3] << 16),
                         (uint32_t)lu[4] | ((uint32_t)lu[5] << 16),
                         (uint32_t)lu[6] | ((uint32_t)lu[7] << 16));
    };
    auto store_stage = [&](int dst, const uint4& pAh, const uint4& pAl,
                           const uint4& pBh, const uint4& pBl) {
        *(uint4*)(Ahi[dst] + arow * BSTU + ahalf * 8) = pAh;
        *(uint4*)(Alo[dst] + arow * BSTU + ahalf * 8) = pAl;
        *(uint4*)(Bhi[dst] + px * BSTU + bh * 8) = pBh;
        *(uint4*)(Blo[dst] + px * BSTU + bh * 8) = pBl;
    };

    {
        uint4 a0, a1, b0, b1;
        prefetch(0, a0, a1, b0, b1);
        store_stage(0, a0, a1, b0, b1);
    }
    __syncthreads();

    int s = 0;
    for (int it = 0; it < NIT; ++it) {
        uint4 pAh, pAl, pBh, pBl;
        const bool has_next = (it + 1 < NIT);
        if (has_next) prefetch(it + 1, pAh, pAl, pBh, pBl);

        uint32_t fAh[2][4], fAl[2][4];
        ldm_x4(fAh[0], aHiS[s]);
        ldm_x4(fAh[1], aHiS[s] + 16 * 48);
        ldm_x4(fAl[0], aLoS[s]);
        ldm_x4(fAl[1], aLoS[s] + 16 * 48);

#pragma unroll
        for (int pt = 0; pt < 4; ++pt) {
            uint32_t fBh[4], fBl[4];
            const uint32_t boff = (uint32_t)((nq * 64 + pt * 16) * 48);
            ldm_x4(fBh, bHiS[s] + boff);
            ldm_x4(fBl, bLoS[s] + boff);
#pragma unroll
            for (int f = 0; f < 2; ++f) {
                mma_bf16(acc[f * 8 + 2 * pt], fAh[f], fBh[0], fBh[1]);
                mma_bf16(acc[f * 8 + 2 * pt], fAh[f], fBl[0], fBl[1]);
                mma_bf16(acc[f * 8 + 2 * pt], fAl[f], fBh[0], fBh[1]);
                mma_bf16(acc[f * 8 + 2 * pt + 1], fAh[f], fBh[2], fBh[3]);
                mma_bf16(acc[f * 8 + 2 * pt + 1], fAh[f], fBl[2], fBl[3]);
                mma_bf16(acc[f * 8 + 2 * pt + 1], fAl[f], fBh[2], fBh[3]);
            }
        }

        if (has_next) store_stage(s ^ 1, pAh, pAl, pBh, pBl);
        __syncthreads();
        s ^= 1;
    }

    // ---- epilogue ----
    const int r = lid >> 2;
    const int q = lid & 3;
#pragma unroll
    for (int f = 0; f < 2; ++f) {
        const int oA = m0 + f * 16 + r;
        const int oB = oA + 8;
        const float bvA = __ldg(bias + oA);
        const float bvB = __ldg(bias + oB);
        float* baseA = out + ((size_t)(bimg * OO + oA)) * HW + p0 + nq * 64 + 2 * q;
        float* baseB = out + ((size_t)(bimg * OO + oB)) * HW + p0 + nq * 64 + 2 * q;
#pragma unroll
        for (int nt = 0; nt < 8; ++nt) {
            const int ai = f * 8 + nt;
            float2 rA, rB;
            rA.x = acc[ai][0] + bvA; rA.y = acc[ai][1] + bvA;
            rB.x = acc[ai][2] + bvB; rB.y = acc[ai][3] + bvB;
            *(float2*)(baseA + nt * 8) = rA;
            *(float2*)(baseB + nt * 8) = rB;
        }
    }
}

// ============================================================================
extern "C" void kernel_launch(void* const* d_in, const int* in_sizes, int n_in,
                              void* d_out, int out_size) {
    const float* x      = (const float*)d_in[0];   // (8,128,64,64)
    const float* w_om   = (const float*)d_in[1];   // (27,128,3,3)
    const float* b_om   = (const float*)d_in[2];   // (27,)
    const float* weight = (const float*)d_in[3];   // (128,128,3,3)
    const float* bias   = (const float*)d_in[4];   // (128,)
    float* out = (float*)d_out;                    // (8,128,64,64)

    prep_all<<<((OO + OMM) * CKK + 255) / 256, 256>>>(weight, w_om);
    om_gemm<<<NPIX / 64, 256>>>(x, b_om);
    gemm_mma<<<NPIX / 128, 256>>>(x, bias, out);
}